// round 1
// baseline (speedup 1.0000x reference)
#include <cuda_runtime.h>
#include <cuda_bf16.h>

#define U      128
#define NSEG0  32
#define NSEG1  8
#define NSEG2  32
#define NPATH  128
#define ZTOT   16384

// CSR path table, sorted by idx_out (built by prep kernel each launch).
__device__ int   g_off[NSEG2 + 1];
__device__ int   g_pi0[NPATH];   // idx0[p] * U (pre-scaled)
__device__ int   g_pi1[NPATH];   // idx1[p] * U
__device__ float g_pc [NPATH];   // coeffs[p]

// Single-warp preprocessing: counting sort of 128 paths by idx_out.
__global__ void tp_prep_kernel(const float* __restrict__ coeffs,
                               const int*   __restrict__ idx0,
                               const int*   __restrict__ idx1,
                               const int*   __restrict__ idx_out) {
    if (threadIdx.x != 0) return;
    int cnt[NSEG2];
    #pragma unroll
    for (int o = 0; o < NSEG2; o++) cnt[o] = 0;
    for (int p = 0; p < NPATH; p++) cnt[idx_out[p]]++;
    int off = 0;
    for (int o = 0; o < NSEG2; o++) {
        g_off[o] = off;
        off += cnt[o];
        cnt[o] = g_off[o];
    }
    g_off[NSEG2] = off;
    for (int p = 0; p < NPATH; p++) {
        int o   = idx_out[p];
        int pos = cnt[o]++;
        g_pi0[pos] = idx0[p] * U;
        g_pi1[pos] = idx1[p] * U;
        g_pc [pos] = coeffs[p];
    }
}

// One block per z-row; 128 threads, one u-lane each.
// Stage x0/x1 rows in smem (each HBM byte read once), accumulate each output
// segment in a register, store coalesced.
__global__ __launch_bounds__(128) void tp_main_kernel(
    const float* __restrict__ x0,
    const float* __restrict__ x1,
    float*       __restrict__ out)
{
    __shared__ float s_x0[NSEG0 * U];  // 16 KB
    __shared__ float s_x1[NSEG1 * U];  //  4 KB
    __shared__ int   s_i0[NPATH];
    __shared__ int   s_i1[NPATH];
    __shared__ float s_c [NPATH];
    __shared__ int   s_off[NSEG2 + 1];

    const int z = blockIdx.x;
    const int u = threadIdx.x;

    // Stage path table (broadcast-cached in L2 across all 16384 blocks).
    s_i0[u] = g_pi0[u];
    s_i1[u] = g_pi1[u];
    s_c [u] = g_pc [u];
    if (u <= NSEG2) s_off[u] = g_off[u];

    // Stage this z-row of x0 (1024 float4) and x1 (256 float4), coalesced.
    const float4* x0v = (const float4*)(x0 + (size_t)z * (NSEG0 * U));
    const float4* x1v = (const float4*)(x1 + (size_t)z * (NSEG1 * U));
    float4* s0v = (float4*)s_x0;
    float4* s1v = (float4*)s_x1;
    #pragma unroll
    for (int k = 0; k < (NSEG0 * U / 4) / 128; k++)   // 8 iters
        s0v[k * 128 + u] = x0v[k * 128 + u];
    #pragma unroll
    for (int k = 0; k < (NSEG1 * U / 4) / 128; k++)   // 2 iters
        s1v[k * 128 + u] = x1v[k * 128 + u];
    __syncthreads();

    float* o_row = out + (size_t)z * (NSEG2 * U);
    #pragma unroll 1
    for (int o = 0; o < NSEG2; o++) {
        float acc = 0.0f;
        const int beg = s_off[o];
        const int end = s_off[o + 1];
        for (int j = beg; j < end; j++) {
            // s_i0/s_i1/s_c reads are warp-uniform broadcasts (no conflicts);
            // s_x0/s_x1 reads are consecutive-u within the warp (no conflicts).
            acc = fmaf(s_c[j] * s_x0[s_i0[j] + u], s_x1[s_i1[j] + u], acc);
        }
        o_row[o * U + u] = acc;  // coalesced 128B per warp
    }
}

extern "C" void kernel_launch(void* const* d_in, const int* in_sizes, int n_in,
                              void* d_out, int out_size) {
    const float* x0      = (const float*)d_in[0];
    const float* x1      = (const float*)d_in[1];
    const float* coeffs  = (const float*)d_in[2];
    const int*   idx0    = (const int*)  d_in[3];
    const int*   idx1    = (const int*)  d_in[4];
    const int*   idx_out = (const int*)  d_in[5];
    float*       out     = (float*)d_out;

    tp_prep_kernel<<<1, 32>>>(coeffs, idx0, idx1, idx_out);
    tp_main_kernel<<<ZTOT, 128>>>(x0, x1, out);
}

// round 2
// speedup vs baseline: 1.0812x; 1.0812x over previous
#include <cuda_runtime.h>
#include <cuda_bf16.h>

#define U      128
#define NSEG0  32
#define NSEG1  8
#define NSEG2  32
#define NPATH  128
#define ZTOT   16384
#define ZB     2

// CSR path table, sorted by idx_out (built by prep kernel each launch).
// meta = {idx0*U, idx1*U, coeff_as_int, 0} -> single uniform LDS.128.
__device__ int4 g_meta[NPATH];
__device__ int  g_off[NSEG2 + 1];

__global__ void tp_prep_kernel(const float* __restrict__ coeffs,
                               const int*   __restrict__ idx0,
                               const int*   __restrict__ idx1,
                               const int*   __restrict__ idx_out) {
    if (threadIdx.x != 0) return;
    int cnt[NSEG2];
    #pragma unroll
    for (int o = 0; o < NSEG2; o++) cnt[o] = 0;
    for (int p = 0; p < NPATH; p++) cnt[idx_out[p]]++;
    int off = 0;
    for (int o = 0; o < NSEG2; o++) {
        g_off[o] = off;
        off += cnt[o];
        cnt[o] = g_off[o];
    }
    g_off[NSEG2] = off;
    for (int p = 0; p < NPATH; p++) {
        int o   = idx_out[p];
        int pos = cnt[o]++;
        g_meta[pos] = make_int4(idx0[p] * U, idx1[p] * U,
                                __float_as_int(coeffs[p]), 0);
    }
}

// One block = ZB z-rows; 128 threads, one u-lane each.
// Smem layout is z-interleaved: s_x0[seg*U + u] = {row z0 val, row z1 val}.
// Inner loop: 1 uniform LDS.128 (meta) + 2 LDS.64 (data) per path for 2 rows.
__global__ __launch_bounds__(128, 5) void tp_main_kernel(
    const float* __restrict__ x0,
    const float* __restrict__ x1,
    float*       __restrict__ out)
{
    __shared__ float2 s_x0[NSEG0 * U];   // 32 KB
    __shared__ float2 s_x1[NSEG1 * U];   //  8 KB
    __shared__ int4   s_meta[NPATH];     //  2 KB
    __shared__ int    s_off[NSEG2 + 1];

    const int u = threadIdx.x;
    const size_t z0 = (size_t)blockIdx.x * ZB;

    // Stage path table (L2-resident, broadcast across 8192 blocks).
    s_meta[u] = g_meta[u];
    if (u <= NSEG2) s_off[u] = g_off[u];

    // Stage x0: rows z0, z0+1 -> interleaved float2. float4 global loads.
    {
        const float4* a0 = (const float4*)(x0 + z0 * (NSEG0 * U));
        const float4* a1 = a0 + (NSEG0 * U / 4);
        #pragma unroll
        for (int k = 0; k < (NSEG0 * U / 4) / 128; k++) {   // 8 iters
            const int idx = k * 128 + u;
            float4 r0 = a0[idx];
            float4 r1 = a1[idx];
            const int b = idx * 4;
            s_x0[b + 0] = make_float2(r0.x, r1.x);
            s_x0[b + 1] = make_float2(r0.y, r1.y);
            s_x0[b + 2] = make_float2(r0.z, r1.z);
            s_x0[b + 3] = make_float2(r0.w, r1.w);
        }
    }
    // Stage x1 likewise.
    {
        const float4* b0 = (const float4*)(x1 + z0 * (NSEG1 * U));
        const float4* b1 = b0 + (NSEG1 * U / 4);
        #pragma unroll
        for (int k = 0; k < (NSEG1 * U / 4) / 128; k++) {   // 2 iters
            const int idx = k * 128 + u;
            float4 r0 = b0[idx];
            float4 r1 = b1[idx];
            const int b = idx * 4;
            s_x1[b + 0] = make_float2(r0.x, r1.x);
            s_x1[b + 1] = make_float2(r0.y, r1.y);
            s_x1[b + 2] = make_float2(r0.z, r1.z);
            s_x1[b + 3] = make_float2(r0.w, r1.w);
        }
    }
    __syncthreads();

    float* o0 = out + z0 * (NSEG2 * U);
    float* o1 = o0 + NSEG2 * U;

    #pragma unroll 1
    for (int o = 0; o < NSEG2; o++) {
        float2 acc = make_float2(0.0f, 0.0f);
        const int beg = s_off[o];
        const int end = s_off[o + 1];
        for (int j = beg; j < end; j++) {
            int4 m = s_meta[j];                 // uniform broadcast, 1 wavefront
            const float  c = __int_as_float(m.z);
            const float2 a = s_x0[m.x + u];     // consecutive-u, conflict-free
            const float2 b = s_x1[m.y + u];
            acc.x = fmaf(c * a.x, b.x, acc.x);
            acc.y = fmaf(c * a.y, b.y, acc.y);
        }
        o0[o * U + u] = acc.x;                  // coalesced 128B per warp
        o1[o * U + u] = acc.y;
    }
}

extern "C" void kernel_launch(void* const* d_in, const int* in_sizes, int n_in,
                              void* d_out, int out_size) {
    const float* x0      = (const float*)d_in[0];
    const float* x1      = (const float*)d_in[1];
    const float* coeffs  = (const float*)d_in[2];
    const int*   idx0    = (const int*)  d_in[3];
    const int*   idx1    = (const int*)  d_in[4];
    const int*   idx_out = (const int*)  d_in[5];
    float*       out     = (float*)d_out;

    tp_prep_kernel<<<1, 32>>>(coeffs, idx0, idx1, idx_out);
    tp_main_kernel<<<ZTOT / ZB, 128>>>(x0, x1, out);
}